// round 4
// baseline (speedup 1.0000x reference)
#include <cuda_runtime.h>
#include <cstdint>

// ----------------------------------------------------------------------------
// BlockSparseLinear: y[8192,4096] = x[8192,4096] @ W^T + bias
// W block-sparse: 64 row-blocks x 16 nonzero 64x64 col-blocks each.
//
// sm_103 (non-'a') target: tcgen05 is unavailable -> Ampere-style
// mma.sync.m16n8k8 tf32 with register accumulators.
//   - CTA tile: 256 tokens x 64 outs (one row-block), loop 16 col-blocks (K=64 each)
//   - staging LDG fp32 -> cvt.rna.tf32 -> STS (padded stride 68: conflict-free frags)
//   - 8 warps, warp tile 32 (M) x 64 (N)
// ----------------------------------------------------------------------------

static constexpr int IN_F  = 4096;
static constexpr int OUT_F = 4096;
static constexpr int BLKSZ = 64;
static constexpr int KBLK  = 16;
static constexpr int BM    = 256;           // tokens per CTA
static constexpr int NTHREADS = 256;        // 8 warps
static constexpr int APAD  = 68;            // padded row stride (floats)

static constexpr int A_FLOATS = BM * APAD;      // 17408
static constexpr int B_FLOATS = BLKSZ * APAD;   // 4352
static constexpr int DYN_SMEM = (A_FLOATS + B_FLOATS) * 4;  // 87040 B

static __device__ __forceinline__ uint32_t f2tf(float f) {
    uint32_t u;
    asm("cvt.rna.tf32.f32 %0, %1;" : "=r"(u) : "f"(f));
    return u;
}

static __device__ __forceinline__ void mma_tf32_16x8x8(
    float& d0, float& d1, float& d2, float& d3,
    uint32_t a0, uint32_t a1, uint32_t a2, uint32_t a3,
    uint32_t b0, uint32_t b1)
{
    asm volatile(
        "mma.sync.aligned.m16n8k8.row.col.f32.tf32.tf32.f32 "
        "{%0,%1,%2,%3}, {%4,%5,%6,%7}, {%8,%9}, {%0,%1,%2,%3};"
        : "+f"(d0), "+f"(d1), "+f"(d2), "+f"(d3)
        : "r"(a0), "r"(a1), "r"(a2), "r"(a3), "r"(b0), "r"(b1));
}

// ----------------------------------------------------------------------------
// grid = (64 row-blocks [fast], 32 token-tiles). 2 CTAs/SM (87KB smem each):
// staging of one CTA overlaps mma of its SM-mate.
// ----------------------------------------------------------------------------
__global__ __launch_bounds__(NTHREADS, 2)
void bsl_mma_kernel(const float* __restrict__ x,
                    const float* __restrict__ w,
                    const float* __restrict__ bias,
                    const int*   __restrict__ col_idx,
                    float*       __restrict__ out)
{
    extern __shared__ float smem[];
    float* As = smem;                // [BM][APAD], tf32 bits
    float* Bs = smem + A_FLOATS;     // [64][APAD], tf32 bits (row = out n, col = k)

    const int tid = threadIdx.x;
    const int wid = tid >> 5;
    const int lane = tid & 31;
    const int g = lane >> 2;         // group id 0..7
    const int cq = lane & 3;         // 0..3

    const int rb   = blockIdx.x;     // row-block
    const int tok0 = blockIdx.y * BM;

    const int* cols = col_idx + rb * KBLK;

    // Accumulators: 2 m-tiles x 8 n-tiles x 4 floats
    float acc[2][8][4];
    #pragma unroll
    for (int mt = 0; mt < 2; ++mt)
        #pragma unroll
        for (int nt = 0; nt < 8; ++nt)
            #pragma unroll
            for (int r = 0; r < 4; ++r) acc[mt][nt][r] = 0.0f;

    const int warp_m = wid * 32;

    for (int cb = 0; cb < KBLK; ++cb) {
        const int c = cols[cb];

        // ---- stage A: x[tok0..tok0+255, c*64..+63] -> As (tf32 bits) ----
        {
            const float* xsrc = x + (size_t)tok0 * IN_F + (size_t)c * BLKSZ;
            #pragma unroll
            for (int i = 0; i < 16; ++i) {
                const int q   = tid + i * NTHREADS;   // 0..4095 float4 chunks
                const int row = q >> 4;               // 0..255
                const int c4  = (q & 15) << 2;        // 0..60
                float4 v = *reinterpret_cast<const float4*>(xsrc + (size_t)row * IN_F + c4);
                uint4 t;
                t.x = f2tf(v.x); t.y = f2tf(v.y); t.z = f2tf(v.z); t.w = f2tf(v.w);
                *reinterpret_cast<uint4*>(As + row * APAD + c4) = t;
            }
        }
        // ---- stage B: weight block (rb, cb): [n=64][k=64] ----
        {
            const float* wsrc = w + ((size_t)rb * KBLK + cb) * (BLKSZ * BLKSZ);
            #pragma unroll
            for (int i = 0; i < 4; ++i) {
                const int q  = tid + i * NTHREADS;    // 0..1023
                const int n  = q >> 4;                // 0..63
                const int c4 = (q & 15) << 2;
                float4 v = *reinterpret_cast<const float4*>(wsrc + n * BLKSZ + c4);
                uint4 t;
                t.x = f2tf(v.x); t.y = f2tf(v.y); t.z = f2tf(v.z); t.w = f2tf(v.w);
                *reinterpret_cast<uint4*>(Bs + n * APAD + c4) = t;
            }
        }
        __syncthreads();

        // ---- compute: K=64 in 8 steps of k=8 ----
        const uint32_t* Au = reinterpret_cast<const uint32_t*>(As);
        const uint32_t* Bu = reinterpret_cast<const uint32_t*>(Bs);
        #pragma unroll
        for (int k0 = 0; k0 < 64; k0 += 8) {
            // A fragments for 2 m16 tiles
            uint32_t a[2][4];
            #pragma unroll
            for (int mt = 0; mt < 2; ++mt) {
                const int r0 = warp_m + mt * 16 + g;
                a[mt][0] = Au[(r0    ) * APAD + k0 + cq    ];
                a[mt][1] = Au[(r0 + 8) * APAD + k0 + cq    ];
                a[mt][2] = Au[(r0    ) * APAD + k0 + cq + 4];
                a[mt][3] = Au[(r0 + 8) * APAD + k0 + cq + 4];
            }
            // B fragments for 8 n8 tiles
            uint32_t b[8][2];
            #pragma unroll
            for (int nt = 0; nt < 8; ++nt) {
                const int n0 = nt * 8 + g;
                b[nt][0] = Bu[n0 * APAD + k0 + cq    ];
                b[nt][1] = Bu[n0 * APAD + k0 + cq + 4];
            }
            #pragma unroll
            for (int mt = 0; mt < 2; ++mt)
                #pragma unroll
                for (int nt = 0; nt < 8; ++nt)
                    mma_tf32_16x8x8(acc[mt][nt][0], acc[mt][nt][1],
                                    acc[mt][nt][2], acc[mt][nt][3],
                                    a[mt][0], a[mt][1], a[mt][2], a[mt][3],
                                    b[nt][0], b[nt][1]);
        }
        __syncthreads();
    }

    // ---- epilogue: +bias, store fp32 ----
    const float* bsrc = bias + rb * BLKSZ;
    #pragma unroll
    for (int mt = 0; mt < 2; ++mt) {
        const int row0 = tok0 + warp_m + mt * 16 + g;
        #pragma unroll
        for (int nt = 0; nt < 8; ++nt) {
            const int col = nt * 8 + 2 * cq;
            const float2 bv = *reinterpret_cast<const float2*>(bsrc + col);
            float* d0 = out + (size_t)row0 * OUT_F + rb * BLKSZ + col;
            float* d1 = out + (size_t)(row0 + 8) * OUT_F + rb * BLKSZ + col;
            float2 o0, o1;
            o0.x = acc[mt][nt][0] + bv.x;
            o0.y = acc[mt][nt][1] + bv.y;
            o1.x = acc[mt][nt][2] + bv.x;
            o1.y = acc[mt][nt][3] + bv.y;
            *reinterpret_cast<float2*>(d0) = o0;
            *reinterpret_cast<float2*>(d1) = o1;
        }
    }
}

// ----------------------------------------------------------------------------
extern "C" void kernel_launch(void* const* d_in, const int* in_sizes, int n_in,
                              void* d_out, int out_size)
{
    const float* x = nullptr;
    const float* w = nullptr;
    const float* bias = nullptr;
    const int* row_idx = nullptr;
    const int* col_idx = nullptr;

    for (int i = 0; i < n_in; ++i) {
        long s = (long)in_sizes[i];
        if (s == 8192L * 4096L)          x = (const float*)d_in[i];
        else if (s == 1024L * 64L * 64L) w = (const float*)d_in[i];
        else if (s == 4096L)             bias = (const float*)d_in[i];
        else if (s == 1024L) {
            if (!row_idx) row_idx = (const int*)d_in[i];
            else          col_idx = (const int*)d_in[i];
        }
    }
    if (!x || !w || !bias || !col_idx) {   // positional fallback
        x       = (const float*)d_in[0];
        w       = (const float*)d_in[1];
        bias    = (const float*)d_in[2];
        row_idx = (const int*)d_in[3];
        col_idx = (const int*)d_in[4];
    }
    (void)row_idx; (void)out_size;

    cudaFuncSetAttribute(bsl_mma_kernel,
                         cudaFuncAttributeMaxDynamicSharedMemorySize, DYN_SMEM);

    dim3 grid(64, 32);   // x = row-block (fast, shares x tiles via L2), y = token tile
    bsl_mma_kernel<<<grid, NTHREADS, DYN_SMEM>>>(x, w, bias, col_idx, (float*)d_out);
}